// round 8
// baseline (speedup 1.0000x reference)
#include <cuda_runtime.h>
#include <cstdint>

#define NT  8192
#define DIM 512
#define HID 2048
#define NE  4
#define BM  128
#define BN  64
#define BK  32

// ---------------- device scratch (no allocs allowed) ----------------
__device__ __align__(16) int   g_cnt[NE];
__device__ __align__(16) int   g_tok[NE * NT];
__device__ __align__(16) int   g_slot[NT * 2];
__device__ __align__(16) float g_gval[NT * 2];
__device__ __align__(16) float g_mid[(size_t)NE * NT * HID];
__device__ __align__(16) float g_y[(size_t)NE * NT * DIM];

typedef unsigned long long ull;

__device__ __forceinline__ void ffma2(ull& d, ull a, ull b) {
    asm("fma.rn.f32x2 %0, %1, %2, %0;" : "+l"(d) : "l"(a), "l"(b));
}
__device__ __forceinline__ ull bcast2(float x) {
    ull r; uint32_t u = __float_as_uint(x);
    asm("mov.b64 %0, {%1, %2};" : "=l"(r) : "r"(u), "r"(u));
    return r;
}
__device__ __forceinline__ float2 unpack2(ull p) {
    uint32_t lo, hi;
    asm("mov.b64 {%0, %1}, %2;" : "=r"(lo), "=r"(hi) : "l"(p));
    return make_float2(__uint_as_float(lo), __uint_as_float(hi));
}

// ---------------- reset ----------------
__global__ void reset_kernel() {
    if (threadIdx.x < NE) g_cnt[threadIdx.x] = 0;
}

// ---------------- gating (proven) ----------------
__global__ void gate_kernel(const float* __restrict__ h,
                            const float* __restrict__ wg) {
    int gw   = (blockIdx.x * blockDim.x + threadIdx.x) >> 5;
    int lane = threadIdx.x & 31;
    if (gw >= NT) return;
    const float* hr = h + (size_t)gw * DIM;
    float a0 = 0.f, a1 = 0.f, a2 = 0.f, a3 = 0.f;
    for (int i = lane; i < DIM; i += 32) {
        float  hv = hr[i];
        float4 w  = reinterpret_cast<const float4*>(wg)[i];
        a0 += hv * w.x; a1 += hv * w.y; a2 += hv * w.z; a3 += hv * w.w;
    }
    #pragma unroll
    for (int o = 16; o; o >>= 1) {
        a0 += __shfl_xor_sync(0xffffffffu, a0, o);
        a1 += __shfl_xor_sync(0xffffffffu, a1, o);
        a2 += __shfl_xor_sync(0xffffffffu, a2, o);
        a3 += __shfl_xor_sync(0xffffffffu, a3, o);
    }
    if (lane == 0) {
        float l[4] = {a0, a1, a2, a3};
        int i0 = 0;
        #pragma unroll
        for (int e = 1; e < 4; e++) if (l[e] > l[i0]) i0 = e;
        int i1 = -1;
        #pragma unroll
        for (int e = 0; e < 4; e++)
            if (e != i0 && (i1 < 0 || l[e] > l[i1])) i1 = e;
        float p1  = expf(l[i1] - l[i0]);
        float inv = 1.0f / (1.0f + p1);
        int p = atomicAdd(&g_cnt[i0], 1);
        g_tok[i0 * NT + p] = gw;
        g_slot[gw * 2]     = i0 * NT + p;
        g_gval[gw * 2]     = inv;
        int q = atomicAdd(&g_cnt[i1], 1);
        g_tok[i1 * NT + q] = gw;
        g_slot[gw * 2 + 1] = i1 * NT + q;
        g_gval[gw * 2 + 1] = p1 * inv;
    }
}

// ---------------- grouped GEMM: BM=128, BN=64, BK=32, 128 threads, 1 barrier/iter ----------------
// Thread microtile 8Mx8N (n contiguous). acc[i][q] = rows tm0+i, col pair (cb8+2q, cb8+2q+1).
template<int KTOT, int NTOT, bool GATHER, bool RELU>
__global__ void __launch_bounds__(128, 4) gemm_kernel(const float* __restrict__ Ain,
                                                      const float* __restrict__ Bg,
                                                      const float* __restrict__ bias) {
    const int e   = blockIdx.z;
    const int cnt = g_cnt[e];
    const int m0  = blockIdx.y * BM;
    if (m0 >= cnt) return;
    const int n0  = blockIdx.x * BN;

    const float* Ag = GATHER ? Ain : g_mid;
    float* outp     = RELU ? g_mid : g_y;

    __shared__ float As[2][BK][BM];   // 32 KB
    __shared__ float Bs[2][BK][BN];   // 16 KB  (total 48 KB exactly)

    const int tid = threadIdx.x;

    // A loader: one row per thread (lm = tid), BK floats per tile (8 x float4)
    const int lm = tid;
    int arow = m0 + lm; if (arow >= cnt) arow = cnt - 1;
    const float* aptr;
    if (GATHER) aptr = Ag + (size_t)g_tok[e * NT + arow] * KTOT;
    else        aptr = Ag + ((size_t)e * NT + arow) * KTOT;

    // B loader: row kb = tid>>2, 4 chunks of 4 floats at cols 4*(tid&3) + 16*j
    const int kb = tid >> 2, bc = (tid & 3) * 4;
    const float* bptr = Bg + (size_t)e * KTOT * NTOT + (size_t)kb * NTOT + n0 + bc;

    // compute mapping
    const int tm0 = (tid >> 3) * 8;   // 16 m-groups
    const int cb8 = (tid & 7) * 8;    // 8 n-groups (contiguous 8 cols)

    ull acc[8][4];
    #pragma unroll
    for (int i = 0; i < 8; i++)
        #pragma unroll
        for (int q = 0; q < 4; q++) acc[i][q] = 0ull;

    const int KT = KTOT / BK;

    // prologue: tile 0 -> stage 0
    {
        #pragma unroll
        for (int j = 0; j < 8; j++) {
            float4 v = *reinterpret_cast<const float4*>(aptr + j * 4);
            As[0][j * 4 + 0][lm] = v.x; As[0][j * 4 + 1][lm] = v.y;
            As[0][j * 4 + 2][lm] = v.z; As[0][j * 4 + 3][lm] = v.w;
        }
        #pragma unroll
        for (int j = 0; j < 4; j++)
            *reinterpret_cast<float4*>(&Bs[0][kb][bc + 16 * j]) =
                *reinterpret_cast<const float4*>(bptr + 16 * j);
    }
    __syncthreads();

    for (int kt = 0; kt < KT; kt++) {
        const int s = kt & 1;

        // stage tile kt+1 into s^1 (no one reads s^1 this iteration)
        if (kt + 1 < KT) {
            const float* ap = aptr + (kt + 1) * BK;
            const float* bp = bptr + (size_t)(kt + 1) * BK * NTOT;
            #pragma unroll
            for (int j = 0; j < 8; j++) {
                float4 v = *reinterpret_cast<const float4*>(ap + j * 4);
                As[s ^ 1][j * 4 + 0][lm] = v.x; As[s ^ 1][j * 4 + 1][lm] = v.y;
                As[s ^ 1][j * 4 + 2][lm] = v.z; As[s ^ 1][j * 4 + 3][lm] = v.w;
            }
            #pragma unroll
            for (int j = 0; j < 4; j++)
                *reinterpret_cast<float4*>(&Bs[s ^ 1][kb][bc + 16 * j]) =
                    *reinterpret_cast<const float4*>(bp + 16 * j);
        }

        // compute stage s
        #pragma unroll
        for (int k = 0; k < BK; k++) {
            float4 a0 = *reinterpret_cast<const float4*>(&As[s][k][tm0]);
            float4 a1 = *reinterpret_cast<const float4*>(&As[s][k][tm0 + 4]);
            ull bv0 = *reinterpret_cast<const ull*>(&Bs[s][k][cb8]);
            ull bv1 = *reinterpret_cast<const ull*>(&Bs[s][k][cb8 + 2]);
            ull bv2 = *reinterpret_cast<const ull*>(&Bs[s][k][cb8 + 4]);
            ull bv3 = *reinterpret_cast<const ull*>(&Bs[s][k][cb8 + 6]);
            ull av;
            av = bcast2(a0.x);
            ffma2(acc[0][0], av, bv0); ffma2(acc[0][1], av, bv1);
            ffma2(acc[0][2], av, bv2); ffma2(acc[0][3], av, bv3);
            av = bcast2(a0.y);
            ffma2(acc[1][0], av, bv0); ffma2(acc[1][1], av, bv1);
            ffma2(acc[1][2], av, bv2); ffma2(acc[1][3], av, bv3);
            av = bcast2(a0.z);
            ffma2(acc[2][0], av, bv0); ffma2(acc[2][1], av, bv1);
            ffma2(acc[2][2], av, bv2); ffma2(acc[2][3], av, bv3);
            av = bcast2(a0.w);
            ffma2(acc[3][0], av, bv0); ffma2(acc[3][1], av, bv1);
            ffma2(acc[3][2], av, bv2); ffma2(acc[3][3], av, bv3);
            av = bcast2(a1.x);
            ffma2(acc[4][0], av, bv0); ffma2(acc[4][1], av, bv1);
            ffma2(acc[4][2], av, bv2); ffma2(acc[4][3], av, bv3);
            av = bcast2(a1.y);
            ffma2(acc[5][0], av, bv0); ffma2(acc[5][1], av, bv1);
            ffma2(acc[5][2], av, bv2); ffma2(acc[5][3], av, bv3);
            av = bcast2(a1.z);
            ffma2(acc[6][0], av, bv0); ffma2(acc[6][1], av, bv1);
            ffma2(acc[6][2], av, bv2); ffma2(acc[6][3], av, bv3);
            av = bcast2(a1.w);
            ffma2(acc[7][0], av, bv0); ffma2(acc[7][1], av, bv1);
            ffma2(acc[7][2], av, bv2); ffma2(acc[7][3], av, bv3);
        }
        __syncthreads();
    }

    // ---- epilogue: 8 contiguous cols per thread -> 2 x float4 per row ----
    float bb[8];
    #pragma unroll
    for (int j = 0; j < 8; j++) bb[j] = bias[(size_t)e * NTOT + n0 + cb8 + j];

    #pragma unroll
    for (int i = 0; i < 8; i++) {
        const int r = m0 + tm0 + i;
        if (r < cnt) {
            float v[8];
            #pragma unroll
            for (int q = 0; q < 4; q++) {
                float2 p = unpack2(acc[i][q]);
                v[2 * q]     = p.x + bb[2 * q];
                v[2 * q + 1] = p.y + bb[2 * q + 1];
            }
            if (RELU) {
                #pragma unroll
                for (int j = 0; j < 8; j++) v[j] = fmaxf(v[j], 0.f);
            }
            float* orow = outp + ((size_t)e * NT + r) * NTOT + n0 + cb8;
            *reinterpret_cast<float4*>(orow)     = make_float4(v[0], v[1], v[2], v[3]);
            *reinterpret_cast<float4*>(orow + 4) = make_float4(v[4], v[5], v[6], v[7]);
        }
    }
}

// ---------------- combine (proven) ----------------
__global__ void combine_kernel(float* __restrict__ out) {
    int idx = blockIdx.x * blockDim.x + threadIdx.x;
    if (idx >= NT * (DIM / 4)) return;
    int n = idx / (DIM / 4);
    int c = idx % (DIM / 4);
    int   sA = g_slot[n * 2],     sB = g_slot[n * 2 + 1];
    float gA = g_gval[n * 2],     gB = g_gval[n * 2 + 1];
    const float4* y4 = reinterpret_cast<const float4*>(g_y);
    float4 a = y4[(size_t)sA * (DIM / 4) + c];
    float4 b = y4[(size_t)sB * (DIM / 4) + c];
    float4 o;
    o.x = gA * a.x + gB * b.x;
    o.y = gA * a.y + gB * b.y;
    o.z = gA * a.z + gB * b.z;
    o.w = gA * a.w + gB * b.w;
    reinterpret_cast<float4*>(out)[idx] = o;
}

// ---------------- launch ----------------
extern "C" void kernel_launch(void* const* d_in, const int* in_sizes, int n_in,
                              void* d_out, int out_size) {
    const float* h  = (const float*)d_in[0];   // [NT, DIM]
    const float* wg = (const float*)d_in[1];   // [DIM, NE]
    const float* w1 = (const float*)d_in[2];   // [NE, DIM, HID]
    const float* b1 = (const float*)d_in[3];   // [NE, HID]
    const float* w2 = (const float*)d_in[4];   // [NE, HID, DIM]
    const float* b2 = (const float*)d_in[5];   // [NE, DIM]
    float* out = (float*)d_out;                // [NT, DIM]

    reset_kernel<<<1, 32>>>();
    gate_kernel<<<(NT * 32) / 256, 256>>>(h, wg);
    {   // GEMM1: mid = relu(h[tok] @ w1[e] + b1)
        dim3 g(HID / BN, NT / BM, NE);
        gemm_kernel<DIM, HID, true, true><<<g, 128>>>(h, w1, b1);
    }
    {   // GEMM2: y = mid @ w2[e] + b2
        dim3 g(DIM / BN, NT / BM, NE);
        gemm_kernel<HID, DIM, false, false><<<g, 128>>>(h /*unused*/, w2, b2);
    }
    combine_kernel<<<(NT * (DIM / 4) + 255) / 256, 256>>>(out);
}

// round 10
// speedup vs baseline: 1.0826x; 1.0826x over previous
#include <cuda_runtime.h>
#include <cstdint>

#define NT  8192
#define DIM 512
#define HID 2048
#define NE  4
#define BM  128
#define BN  128
#define BK  16

// ---------------- device scratch (no allocs allowed) ----------------
__device__ __align__(16) int   g_cnt[NE];
__device__ __align__(16) int   g_tok[NE * NT];
__device__ __align__(16) int   g_slot[NT * 2];
__device__ __align__(16) float g_gval[NT * 2];
__device__ __align__(16) float g_mid[(size_t)NE * NT * HID];
__device__ __align__(16) float g_y[(size_t)NE * NT * DIM];

typedef unsigned long long ull;

__device__ __forceinline__ void ffma2(ull& d, ull a, ull b) {
    asm("fma.rn.f32x2 %0, %1, %2, %0;" : "+l"(d) : "l"(a), "l"(b));
}
__device__ __forceinline__ float2 unpack2(ull p) {
    uint32_t lo, hi;
    asm("mov.b64 {%0, %1}, %2;" : "=r"(lo), "=r"(hi) : "l"(p));
    return make_float2(__uint_as_float(lo), __uint_as_float(hi));
}

// ---------------- reset ----------------
__global__ void reset_kernel() {
    if (threadIdx.x < NE) g_cnt[threadIdx.x] = 0;
}

// ---------------- gating (proven) ----------------
__global__ void gate_kernel(const float* __restrict__ h,
                            const float* __restrict__ wg) {
    int gw   = (blockIdx.x * blockDim.x + threadIdx.x) >> 5;
    int lane = threadIdx.x & 31;
    if (gw >= NT) return;
    const float* hr = h + (size_t)gw * DIM;
    float a0 = 0.f, a1 = 0.f, a2 = 0.f, a3 = 0.f;
    for (int i = lane; i < DIM; i += 32) {
        float  hv = hr[i];
        float4 w  = reinterpret_cast<const float4*>(wg)[i];
        a0 += hv * w.x; a1 += hv * w.y; a2 += hv * w.z; a3 += hv * w.w;
    }
    #pragma unroll
    for (int o = 16; o; o >>= 1) {
        a0 += __shfl_xor_sync(0xffffffffu, a0, o);
        a1 += __shfl_xor_sync(0xffffffffu, a1, o);
        a2 += __shfl_xor_sync(0xffffffffu, a2, o);
        a3 += __shfl_xor_sync(0xffffffffu, a3, o);
    }
    if (lane == 0) {
        float l[4] = {a0, a1, a2, a3};
        int i0 = 0;
        #pragma unroll
        for (int e = 1; e < 4; e++) if (l[e] > l[i0]) i0 = e;
        int i1 = -1;
        #pragma unroll
        for (int e = 0; e < 4; e++)
            if (e != i0 && (i1 < 0 || l[e] > l[i1])) i1 = e;
        float p1  = expf(l[i1] - l[i0]);
        float inv = 1.0f / (1.0f + p1);
        int p = atomicAdd(&g_cnt[i0], 1);
        g_tok[i0 * NT + p] = gw;
        g_slot[gw * 2]     = i0 * NT + p;
        g_gval[gw * 2]     = inv;
        int q = atomicAdd(&g_cnt[i1], 1);
        g_tok[i1 * NT + q] = gw;
        g_slot[gw * 2 + 1] = i1 * NT + q;
        g_gval[gw * 2 + 1] = p1 * inv;
    }
}

// ---------------- grouped GEMM: R7 shapes + duplicated-A smem + 1 barrier/tile ----------------
// BM=128, BN=128, BK=16, 256 threads, microtile 8x8 (n as 4 pairs at tnb+32q).
template<int KTOT, int NTOT, bool GATHER, bool RELU>
__global__ void __launch_bounds__(256) gemm_kernel(const float* __restrict__ Ain,
                                                   const float* __restrict__ Bg,
                                                   const float* __restrict__ bias) {
    const int e   = blockIdx.z;
    const int cnt = g_cnt[e];
    const int m0  = blockIdx.y * BM;
    if (m0 >= cnt) return;
    const int n0  = blockIdx.x * BN;

    const float* Ag = GATHER ? Ain : g_mid;
    float* outp     = RELU ? g_mid : g_y;

    __shared__ float2 As2[2][BK][BM];   // duplicated A: (a,a) -> 32 KB
    __shared__ float  Bs [2][BK][BN];   // 16 KB (total exactly 48 KB)

    const int tid = threadIdx.x;

    // A staging: thread -> row lr, k's lk..lk+7 (2 x LDG.128, 8 x STS.64)
    const int lr = tid >> 1, lk = (tid & 1) * 8;
    int arow = m0 + lr; if (arow >= cnt) arow = cnt - 1;
    const float* aptr;
    if (GATHER) aptr = Ag + (size_t)g_tok[e * NT + arow] * KTOT + lk;
    else        aptr = Ag + ((size_t)e * NT + arow) * KTOT + lk;

    // B staging: thread -> k-row kb, 8 cols at bc (2 x LDG.128, 2 x STS.128)
    const int kb = tid >> 4, bc = (tid & 15) * 8;
    const float* bptr = Bg + (size_t)e * KTOT * NTOT + (size_t)kb * NTOT + n0 + bc;

    // compute mapping (proven R7): rows tm0..tm0+7, col pairs tnb+32q
    const int tm0 = (tid >> 4) * 8;
    const int tnb = (tid & 15) * 2;

    ull acc[8][4];
    #pragma unroll
    for (int i = 0; i < 8; i++)
        #pragma unroll
        for (int q = 0; q < 4; q++) acc[i][q] = 0ull;

    const int KT = KTOT / BK;

    float4 pa0, pa1, pb0, pb1;

    // load tile 0 -> regs
    pa0 = *reinterpret_cast<const float4*>(aptr);
    pa1 = *reinterpret_cast<const float4*>(aptr + 4);
    pb0 = *reinterpret_cast<const float4*>(bptr);
    pb1 = *reinterpret_cast<const float4*>(bptr + 4);

    // store tile 0 -> stage 0
    {
        float a_[8] = {pa0.x, pa0.y, pa0.z, pa0.w, pa1.x, pa1.y, pa1.z, pa1.w};
        #pragma unroll
        for (int j = 0; j < 8; j++) As2[0][lk + j][lr] = make_float2(a_[j], a_[j]);
        *reinterpret_cast<float4*>(&Bs[0][kb][bc])     = pb0;
        *reinterpret_cast<float4*>(&Bs[0][kb][bc + 4]) = pb1;
    }

    // load tile 1 -> regs
    if (KT > 1) {
        pa0 = *reinterpret_cast<const float4*>(aptr + BK);
        pa1 = *reinterpret_cast<const float4*>(aptr + BK + 4);
        pb0 = *reinterpret_cast<const float4*>(bptr + (size_t)BK * NTOT);
        pb1 = *reinterpret_cast<const float4*>(bptr + (size_t)BK * NTOT + 4);
    }
    __syncthreads();

    for (int kt = 0; kt < KT; kt++) {
        const int s = kt & 1;

        // store tile kt+1 (in regs) -> stage s^1 (last read finished at barrier of iter kt-1)
        if (kt + 1 < KT) {
            float a_[8] = {pa0.x, pa0.y, pa0.z, pa0.w, pa1.x, pa1.y, pa1.z, pa1.w};
            #pragma unroll
            for (int j = 0; j < 8; j++) As2[s ^ 1][lk + j][lr] = make_float2(a_[j], a_[j]);
            *reinterpret_cast<float4*>(&Bs[s ^ 1][kb][bc])     = pb0;
            *reinterpret_cast<float4*>(&Bs[s ^ 1][kb][bc + 4]) = pb1;
        }
        // issue LDG for tile kt+2 (latency covered by compute below)
        if (kt + 2 < KT) {
            const float* ap = aptr + (kt + 2) * BK;
            const float* bp = bptr + (size_t)(kt + 2) * BK * NTOT;
            pa0 = *reinterpret_cast<const float4*>(ap);
            pa1 = *reinterpret_cast<const float4*>(ap + 4);
            pb0 = *reinterpret_cast<const float4*>(bp);
            pb1 = *reinterpret_cast<const float4*>(bp + 4);
        }

        // compute stage s
        #pragma unroll
        for (int k = 0; k < BK; k++) {
            const ulonglong2* arow4 = reinterpret_cast<const ulonglong2*>(&As2[s][k][0]);
            ull av[8];
            {
                ulonglong2 u;
                u = arow4[(tm0 >> 1) + 0]; av[0] = u.x; av[1] = u.y;
                u = arow4[(tm0 >> 1) + 1]; av[2] = u.x; av[3] = u.y;
                u = arow4[(tm0 >> 1) + 2]; av[4] = u.x; av[5] = u.y;
                u = arow4[(tm0 >> 1) + 3]; av[6] = u.x; av[7] = u.y;
            }
            ull bv0 = *reinterpret_cast<const ull*>(&Bs[s][k][tnb]);
            ull bv1 = *reinterpret_cast<const ull*>(&Bs[s][k][tnb + 32]);
            ull bv2 = *reinterpret_cast<const ull*>(&Bs[s][k][tnb + 64]);
            ull bv3 = *reinterpret_cast<const ull*>(&Bs[s][k][tnb + 96]);
            #pragma unroll
            for (int i = 0; i < 8; i++) {
                ffma2(acc[i][0], av[i], bv0);
                ffma2(acc[i][1], av[i], bv1);
                ffma2(acc[i][2], av[i], bv2);
                ffma2(acc[i][3], av[i], bv3);
            }
        }
        __syncthreads();   // readers of s done before iter kt+1 overwrites s
    }

    // ---- epilogue (proven R7) ----
    #pragma unroll
    for (int i = 0; i < 8; i++) {
        const int r = m0 + tm0 + i;
        if (r < cnt) {
            float* orow = outp + ((size_t)e * NT + r) * NTOT + n0;
            #pragma unroll
            for (int q = 0; q < 4; q++) {
                const int c = tnb + 32 * q;
                float2 v = unpack2(acc[i][q]);
                v.x += bias[(size_t)e * NTOT + n0 + c];
                v.y += bias[(size_t)e * NTOT + n0 + c + 1];
                if (RELU) { v.x = fmaxf(v.x, 0.f); v.y = fmaxf(v.y, 0.f); }
                *reinterpret_cast<float2*>(orow + c) = v;
            }
        }
    }
}

// ---------------- combine (proven) ----------------
__global__ void combine_kernel(float* __restrict__ out) {
    int idx = blockIdx.x * blockDim.x + threadIdx.x;
    if (idx >= NT * (DIM / 4)) return;
    int n = idx / (DIM / 4);
    int c = idx % (DIM / 4);
    int   sA = g_slot[n * 2],     sB = g_slot[n * 2 + 1];
    float gA = g_gval[n * 2],     gB = g_gval[n * 2 + 1];
    const float4* y4 = reinterpret_cast<const float4*>(g_y);
    float4 a = y4[(size_t)sA * (DIM / 4) + c];
    float4 b = y4[(size_t)sB * (DIM / 4) + c];
    float4 o;
    o.x = gA * a.x + gB * b.x;
    o.y = gA * a.y + gB * b.y;
    o.z = gA * a.z + gB * b.z;
    o.w = gA * a.w + gB * b.w;
    reinterpret_cast<float4*>(out)[idx] = o;
}

// ---------------- launch ----------------
extern "C" void kernel_launch(void* const* d_in, const int* in_sizes, int n_in,
                              void* d_out, int out_size) {
    const float* h  = (const float*)d_in[0];   // [NT, DIM]
    const float* wg = (const float*)d_in[1];   // [DIM, NE]
    const float* w1 = (const float*)d_in[2];   // [NE, DIM, HID]
    const float* b1 = (const float*)d_in[3];   // [NE, HID]
    const float* w2 = (const float*)d_in[4];   // [NE, HID, DIM]
    const float* b2 = (const float*)d_in[5];   // [NE, DIM]
    float* out = (float*)d_out;                // [NT, DIM]

    reset_kernel<<<1, 32>>>();
    gate_kernel<<<(NT * 32) / 256, 256>>>(h, wg);
    {   // GEMM1: mid = relu(h[tok] @ w1[e] + b1)
        dim3 g(HID / BN, NT / BM, NE);
        gemm_kernel<DIM, HID, true, true><<<g, 256>>>(h, w1, b1);
    }
    {   // GEMM2: y = mid @ w2[e] + b2
        dim3 g(DIM / BN, NT / BM, NE);
        gemm_kernel<HID, DIM, false, false><<<g, 256>>>(h /*unused*/, w2, b2);
    }
    combine_kernel<<<(NT * (DIM / 4) + 255) / 256, 256>>>(out);
}